// round 6
// baseline (speedup 1.0000x reference)
#include <cuda_runtime.h>
#include <math.h>

// CantorMoELayer — B=8, P=2048, D=1024, E=16, S=64, DK=128, H=16
// R6: widen per-thread GEMV tiles (d-pair / s-pair) to halve smem-broadcast
// LDS wavefronts (the binding L1TEX resource), run gate || V and Vp || rec on
// disjoint thread subsets, and give nact==1 positions the full 256 threads.

namespace {

constexpr int P_  = 2048;
constexpr int D_  = 1024;
constexpr int E_  = 16;
constexpr int S_  = 64;
constexpr int DK_ = 128;
constexpr int H_  = 16;

__device__ __forceinline__ float sigm(float x) { return 1.0f / (1.0f + expf(-x)); }
__device__ __forceinline__ float gelu_exact(float x) {
    return 0.5f * x * (1.0f + erff(x * 0.70710678118654752440f));
}

__global__ void __launch_bounds__(256, 4) cantor_moe_kernel(
    const float* __restrict__ x,
    const float* __restrict__ fingerprints,
    const float* __restrict__ ln_gamma,
    const float* __restrict__ ln_beta,
    const float* __restrict__ w1,
    const float* __restrict__ b1,
    const float* __restrict__ w2,
    const float* __restrict__ b2,
    const float* __restrict__ alpha,
    const float* __restrict__ wv,
    const float* __restrict__ penta,
    const float* __restrict__ betas,
    const float* __restrict__ wout,
    const float* __restrict__ pos_embed,
    const float* __restrict__ temperature,
    float* __restrict__ out)
{
    __shared__ float xnsm[2][8][S_];     // 4 KB: normalized ACTIVE slices
    __shared__ float Vsm[2][8][DK_];     // 8 KB: unscaled V
    __shared__ float recA[2][8][S_];     // 4 KB: rec from d-half 0 (scaled)
    __shared__ float recB[2][8][S_];     // 4 KB: rec from d-half 1 (scaled)
    __shared__ float scalesm[2][8];
    __shared__ float Vpsm[2][8][5];
    __shared__ float w_esm[2];

    const int p    = blockIdx.x;
    const int tid  = threadIdx.x;
    const int warp = tid >> 5;
    const int lane = tid & 31;

    // ---------------- expert selection (redundant per-thread) ----------------
    const float fp = __ldg(fingerprints + p);
    int nact = 0, e0 = 0, e1 = -1;
    {
        const int base = (int)floorf(fp * 16.0f);
#pragma unroll
        for (int dd = -1; dd <= 1; ++dd) {
            const int ee = base + dd;
            if (ee < 0 || ee >= E_) continue;
            const float fmn = fmaxf(0.0f, (float)ee * 0.0625f - 0.03125f);
            const float fmx = fminf(1.0f, (float)(ee + 1) * 0.0625f + 0.03125f);
            if (fp >= fmn && fp < fmx) {
                if (nact == 0) e0 = ee; else if (nact == 1) e1 = ee;
                ++nact;
            }
        }
        if (nact > 2) nact = 2;
        if (nact < 2) e1 = -1;
    }

    // ---------------- LayerNorm: warp w = batch b; 2-pass ----------------
    {
        const int b = warp;
        const float* xr = x + ((size_t)b * P_ + p) * D_;
        float s = 0.f, ss = 0.f;
#pragma unroll
        for (int it = 0; it < 8; ++it) {
            const float4 xv = __ldg((const float4*)xr + it * 32 + lane);
            s  += xv.x + xv.y + xv.z + xv.w;
            ss += xv.x * xv.x + xv.y * xv.y + xv.z * xv.z + xv.w * xv.w;
        }
#pragma unroll
        for (int o = 16; o; o >>= 1) {
            s  += __shfl_xor_sync(~0u, s, o);
            ss += __shfl_xor_sync(~0u, ss, o);
        }
        const float mu   = s * (1.0f / D_);
        const float var  = ss * (1.0f / D_) - mu * mu;
        const float rstd = rsqrtf(var + 1e-5f);
        const int kk = lane >> 4;
        if (kk < nact) {
            const int ee = kk ? e1 : e0;
            const int f4 = ee * 16 + (lane & 15);
            const float4 xv = __ldg((const float4*)xr + f4);
            const float4 gm = __ldg((const float4*)ln_gamma + f4);
            const float4 bt = __ldg((const float4*)ln_beta + f4);
            float4 o4;
            o4.x = (xv.x - mu) * rstd * gm.x + bt.x;
            o4.y = (xv.y - mu) * rstd * gm.y + bt.y;
            o4.z = (xv.z - mu) * rstd * gm.z + bt.z;
            o4.w = (xv.w - mu) * rstd * gm.w + bt.w;
            *(float4*)&xnsm[kk][b][(lane & 15) * 4] = o4;
        }
    }
    __syncthreads();   // sync1

    if (nact == 2) {
        const int k = tid >> 7;          // expert slot
        const int g = tid & 127;
        const int e = k ? e1 : e0;

        // ---------- phase 2: V (g<64, d-pair) || gate (g>=64, j-pair) ----------
        if (g < 64) {
            const int d0 = g * 2;
            const float* WV = wv + e * (S_ * DK_);
            float2 acc[8];
#pragma unroll
            for (int b = 0; b < 8; ++b) acc[b] = make_float2(0.f, 0.f);
#pragma unroll
            for (int s4 = 0; s4 < S_ / 4; ++s4) {
                const float2 q0 = __ldg((const float2*)(WV + (s4 * 4 + 0) * DK_ + d0));
                const float2 q1 = __ldg((const float2*)(WV + (s4 * 4 + 1) * DK_ + d0));
                const float2 q2 = __ldg((const float2*)(WV + (s4 * 4 + 2) * DK_ + d0));
                const float2 q3 = __ldg((const float2*)(WV + (s4 * 4 + 3) * DK_ + d0));
#pragma unroll
                for (int b = 0; b < 8; ++b) {
                    const float4 xf = *(const float4*)&xnsm[k][b][s4 * 4];
                    acc[b].x += xf.x * q0.x + xf.y * q1.x + xf.z * q2.x + xf.w * q3.x;
                    acc[b].y += xf.x * q0.y + xf.y * q1.y + xf.z * q2.y + xf.w * q3.y;
                }
            }
#pragma unroll
            for (int b = 0; b < 8; ++b) *(float2*)&Vsm[k][b][d0] = acc[b];
        } else {
            const int gg = g - 64;            // 0..63
            const int b = gg >> 3, jq = gg & 7;
            const int j0 = jq * 2;
            const float* W1 = w1 + e * (S_ * H_);
            const float2 b1v = __ldg((const float2*)(b1 + e * H_ + j0));
            float a0 = b1v.x, a1 = b1v.y;
#pragma unroll
            for (int s4 = 0; s4 < S_ / 4; ++s4) {
                const float4 xf = *(const float4*)&xnsm[k][b][s4 * 4];
                const float2 q0 = __ldg((const float2*)(W1 + (s4 * 4 + 0) * H_ + j0));
                const float2 q1 = __ldg((const float2*)(W1 + (s4 * 4 + 1) * H_ + j0));
                const float2 q2 = __ldg((const float2*)(W1 + (s4 * 4 + 2) * H_ + j0));
                const float2 q3 = __ldg((const float2*)(W1 + (s4 * 4 + 3) * H_ + j0));
                a0 += xf.x * q0.x + xf.y * q1.x + xf.z * q2.x + xf.w * q3.x;
                a1 += xf.x * q0.y + xf.y * q1.y + xf.z * q2.y + xf.w * q3.y;
            }
            const float2 w2v = __ldg((const float2*)(w2 + e * H_ + j0));
            float t = gelu_exact(a0) * w2v.x + gelu_exact(a1) * w2v.y;
#pragma unroll
            for (int o = 4; o; o >>= 1) t += __shfl_down_sync(~0u, t, o, 8);
            if (jq == 0) {
                const float gate = sigm(t + __ldg(b2 + e));
                const float aw   = sigm(__ldg(alpha + e));
                scalesm[k][b] = gate * aw + (1.0f - aw);
            }
        }
        __syncthreads();   // sync2

        // ---------- phase 3: rec (g<64, s-pair) || Vp + w_e (g>=64) ----------
        if (g < 64) {
            const int s0   = (g & 31) * 2;
            const int half = g >> 5;
            const float* WO = wout + e * (DK_ * S_) + half * 64 * S_;
            float2 acc[8];
#pragma unroll
            for (int b = 0; b < 8; ++b) acc[b] = make_float2(0.f, 0.f);
#pragma unroll
            for (int d4 = 0; d4 < 16; ++d4) {
                const int d = d4 * 4;
                const float2 q0 = __ldg((const float2*)(WO + (d + 0) * S_ + s0));
                const float2 q1 = __ldg((const float2*)(WO + (d + 1) * S_ + s0));
                const float2 q2 = __ldg((const float2*)(WO + (d + 2) * S_ + s0));
                const float2 q3 = __ldg((const float2*)(WO + (d + 3) * S_ + s0));
#pragma unroll
                for (int b = 0; b < 8; ++b) {
                    const float4 vv = *(const float4*)&Vsm[k][b][half * 64 + d];
                    acc[b].x += vv.x * q0.x + vv.y * q1.x + vv.z * q2.x + vv.w * q3.x;
                    acc[b].y += vv.x * q0.y + vv.y * q1.y + vv.z * q2.y + vv.w * q3.y;
                }
            }
            if (half == 0) {
#pragma unroll
                for (int b = 0; b < 8; ++b) {
                    const float sc = scalesm[k][b];
                    recA[k][b][s0]     = acc[b].x * sc;
                    recA[k][b][s0 + 1] = acc[b].y * sc;
                }
            } else {
#pragma unroll
                for (int b = 0; b < 8; ++b) {
                    const float sc = scalesm[k][b];
                    recB[k][b][s0]     = acc[b].x * sc;
                    recB[k][b][s0 + 1] = acc[b].y * sc;
                }
            }
        } else {
            const int wg2 = (g - 64) >> 5;    // 0 or 1
#pragma unroll
            for (int t = 0; t < 20; ++t) {
                const int idx = wg2 * 20 + t;  // 0..39
                const int v = idx >> 3, b = idx & 7;
                const float4 pv = __ldg((const float4*)(penta + (e * 5 + v) * DK_) + lane);
                const float4 vv = *(const float4*)&Vsm[k][b][lane * 4];
                float pd = pv.x * vv.x + pv.y * vv.y + pv.z * vv.z + pv.w * vv.w;
                float nn = pv.x * pv.x + pv.y * pv.y + pv.z * pv.z + pv.w * pv.w;
#pragma unroll
                for (int o = 16; o; o >>= 1) {
                    pd += __shfl_xor_sync(~0u, pd, o);
                    nn += __shfl_xor_sync(~0u, nn, o);
                }
                if (lane == 0)
                    Vpsm[k][b][v] = pd * rsqrtf(nn) * scalesm[k][b];
            }
            if (wg2 == 1) {
                const float4 pe = __ldg((const float4*)(pos_embed + e * DK_) + lane);
                float pm = pe.x + pe.y + pe.z + pe.w;
#pragma unroll
                for (int o = 16; o; o >>= 1) pm += __shfl_xor_sync(~0u, pm, o);
                if (lane == 0) {
                    float sb = 0.f, cnt = 0.f;
#pragma unroll
                    for (int kk = 0; kk < 4; ++kk) {
                        const int off = (kk == 0) ? -2 : (kk == 1) ? -1 : (kk == 2) ? 1 : 2;
                        const int nb = e + off;
                        if (nb >= 0 && nb < E_) { sb += sigm(__ldg(betas + e * 4 + kk)); cnt += 1.f; }
                    }
                    w_esm[k] = sigm(pm * (1.0f / DK_)) * (1.0f + sb / cnt);
                }
            }
        }
    } else {
        // ================= nact == 1: full 256 threads on expert e0 =================
        const int e = e0;
        // ---------- phase 2: V (tid<128, single-d) || gate (tid>=128) ----------
        if (tid < 128) {
            const int d = tid;
            const float* WV = wv + e * (S_ * DK_);
            float acc[8];
#pragma unroll
            for (int b = 0; b < 8; ++b) acc[b] = 0.f;
#pragma unroll
            for (int s4 = 0; s4 < S_ / 4; ++s4) {
                const float q0 = __ldg(WV + (s4 * 4 + 0) * DK_ + d);
                const float q1 = __ldg(WV + (s4 * 4 + 1) * DK_ + d);
                const float q2 = __ldg(WV + (s4 * 4 + 2) * DK_ + d);
                const float q3 = __ldg(WV + (s4 * 4 + 3) * DK_ + d);
#pragma unroll
                for (int b = 0; b < 8; ++b) {
                    const float4 xf = *(const float4*)&xnsm[0][b][s4 * 4];
                    acc[b] += xf.x * q0 + xf.y * q1 + xf.z * q2 + xf.w * q3;
                }
            }
#pragma unroll
            for (int b = 0; b < 8; ++b) Vsm[0][b][d] = acc[b];
        } else {
            const int gg = tid - 128;          // 0..127
            const int b = gg >> 4, j = gg & 15;
            const float* W1 = w1 + e * (S_ * H_);
            float acc = __ldg(b1 + e * H_ + j);
#pragma unroll
            for (int s4 = 0; s4 < S_ / 4; ++s4) {
                const float4 xf = *(const float4*)&xnsm[0][b][s4 * 4];
                acc += xf.x * __ldg(W1 + (s4 * 4 + 0) * H_ + j)
                     + xf.y * __ldg(W1 + (s4 * 4 + 1) * H_ + j)
                     + xf.z * __ldg(W1 + (s4 * 4 + 2) * H_ + j)
                     + xf.w * __ldg(W1 + (s4 * 4 + 3) * H_ + j);
            }
            float t = gelu_exact(acc) * __ldg(w2 + e * H_ + j);
#pragma unroll
            for (int o = 8; o; o >>= 1) t += __shfl_down_sync(~0u, t, o, 16);
            if (j == 0) {
                const float gate = sigm(t + __ldg(b2 + e));
                const float aw   = sigm(__ldg(alpha + e));
                scalesm[0][b] = gate * aw + (1.0f - aw);
            }
        }
        __syncthreads();   // sync2

        // ---------- phase 3: rec (tid<128, single-s) || Vp + w_e (tid>=128) ----------
        if (tid < 128) {
            const int s_idx = tid & 63, half = tid >> 6;
            const float* WO = wout + e * (DK_ * S_) + half * 64 * S_;
            float racc[8];
#pragma unroll
            for (int b = 0; b < 8; ++b) racc[b] = 0.f;
#pragma unroll
            for (int d4 = 0; d4 < 16; ++d4) {
                const int d = d4 * 4;
                const float q0 = __ldg(WO + (d + 0) * S_ + s_idx);
                const float q1 = __ldg(WO + (d + 1) * S_ + s_idx);
                const float q2 = __ldg(WO + (d + 2) * S_ + s_idx);
                const float q3 = __ldg(WO + (d + 3) * S_ + s_idx);
#pragma unroll
                for (int b = 0; b < 8; ++b) {
                    const float4 vv = *(const float4*)&Vsm[0][b][half * 64 + d];
                    racc[b] += vv.x * q0 + vv.y * q1 + vv.z * q2 + vv.w * q3;
                }
            }
            if (half == 0) {
#pragma unroll
                for (int b = 0; b < 8; ++b) recA[0][b][s_idx] = racc[b] * scalesm[0][b];
            } else {
#pragma unroll
                for (int b = 0; b < 8; ++b) recB[0][b][s_idx] = racc[b] * scalesm[0][b];
            }
        } else {
            const int wg = (tid - 128) >> 5;   // 0..3
#pragma unroll
            for (int t = 0; t < 10; ++t) {
                const int idx = wg * 10 + t;   // 0..39
                const int v = idx >> 3, b = idx & 7;
                const float4 pv = __ldg((const float4*)(penta + (e * 5 + v) * DK_) + lane);
                const float4 vv = *(const float4*)&Vsm[0][b][lane * 4];
                float pd = pv.x * vv.x + pv.y * vv.y + pv.z * vv.z + pv.w * vv.w;
                float nn = pv.x * pv.x + pv.y * pv.y + pv.z * pv.z + pv.w * pv.w;
#pragma unroll
                for (int o = 16; o; o >>= 1) {
                    pd += __shfl_xor_sync(~0u, pd, o);
                    nn += __shfl_xor_sync(~0u, nn, o);
                }
                if (lane == 0)
                    Vpsm[0][b][v] = pd * rsqrtf(nn) * scalesm[0][b];
            }
            if (wg == 0) {
                const float4 pe = __ldg((const float4*)(pos_embed + e * DK_) + lane);
                float pm = pe.x + pe.y + pe.z + pe.w;
#pragma unroll
                for (int o = 16; o; o >>= 1) pm += __shfl_xor_sync(~0u, pm, o);
                if (lane == 0) {
                    float sb = 0.f, cnt = 0.f;
#pragma unroll
                    for (int kk = 0; kk < 4; ++kk) {
                        const int off = (kk == 0) ? -2 : (kk == 1) ? -1 : (kk == 2) ? 1 : 2;
                        const int nb = e + off;
                        if (nb >= 0 && nb < E_) { sb += sigm(__ldg(betas + e * 4 + kk)); cnt += 1.f; }
                    }
                    w_esm[0] = sigm(pm * (1.0f / DK_)) * (1.0f + sb / cnt);
                }
            }
        }
    }
    __syncthreads();   // sync3

    // -------- epilogue: inline fused; out = x + fused * rec on active slices --------
    {
        const int b = tid >> 5;              // one warp per batch
        float den = 0.f;
        for (int kk = 0; kk < nact; ++kk) den += w_esm[kk];
        den = fmaxf(den, 1e-6f);
        float fs = 0.f;
#pragma unroll
        for (int v = 0; v < 5; ++v) {
            float nv = 0.f;
            for (int kk = 0; kk < nact; ++kk) nv += Vpsm[kk][b][v] * w_esm[kk];
            fs += nv;
        }
        const float fused = (fs / den) * 0.2f / fabsf(__ldg(temperature));

        const float* xr  = x   + ((size_t)b * P_ + p) * D_;
        float*       orw = out + ((size_t)b * P_ + p) * D_;
#pragma unroll
        for (int it = 0; it < 8; ++it) {
            const int f4 = it * 32 + lane;
            float4 xv = __ldg((const float4*)xr + f4);
            const int ee = f4 >> 4;
            const int kk = (ee == e0) ? 0 : ((ee == e1) ? 1 : -1);
            if (kk >= 0) {
                const int si = (f4 & 15) * 4;
                const float4 ra = *(const float4*)&recA[kk][b][si];
                const float4 rb = *(const float4*)&recB[kk][b][si];
                xv.x += fused * (ra.x + rb.x);
                xv.y += fused * (ra.y + rb.y);
                xv.z += fused * (ra.z + rb.z);
                xv.w += fused * (ra.w + rb.w);
            }
            ((float4*)orw)[f4] = xv;
        }
    }
}

} // namespace

extern "C" void kernel_launch(void* const* d_in, const int* in_sizes, int n_in,
                              void* d_out, int out_size)
{
    (void)in_sizes; (void)n_in; (void)out_size;
    cantor_moe_kernel<<<P_, 256>>>(
        (const float*)d_in[0],   // x
        (const float*)d_in[1],   // fingerprints
        (const float*)d_in[2],   // ln_gamma
        (const float*)d_in[3],   // ln_beta
        (const float*)d_in[4],   // w1
        (const float*)d_in[5],   // b1
        (const float*)d_in[6],   // w2
        (const float*)d_in[7],   // b2
        (const float*)d_in[8],   // alpha
        (const float*)d_in[9],   // wv
        (const float*)d_in[10],  // penta
        (const float*)d_in[11],  // betas
        (const float*)d_in[12],  // wout
        (const float*)d_in[13],  // pos_embed
        (const float*)d_in[14],  // temperature
        (float*)d_out);
}

// round 7
// speedup vs baseline: 1.6314x; 1.6314x over previous
#include <cuda_runtime.h>
#include <math.h>

// CantorMoELayer — B=8, P=2048, D=1024, E=16, S=64, DK=128, H=16
// R7: back to R5's 128-thread GEMVs (R6's 64-thread wide tiles were a latency
// regression), now with packed fma.rn.f32x2 in the V/rec GEMVs (~32% fewer
// instrs in the hot loops), float4 gate loads, hoisted+deduped Vp norms, and
// the full-256-thread nact==1 path kept from R6.

namespace {

constexpr int P_  = 2048;
constexpr int D_  = 1024;
constexpr int E_  = 16;
constexpr int S_  = 64;
constexpr int DK_ = 128;
constexpr int H_  = 16;

typedef unsigned long long ull;

__device__ __forceinline__ float sigm(float x) { return 1.0f / (1.0f + expf(-x)); }
__device__ __forceinline__ float gelu_exact(float x) {
    return 0.5f * x * (1.0f + erff(x * 0.70710678118654752440f));
}
__device__ __forceinline__ ull pk(float a, float b) {
    ull r;
    asm("mov.b64 %0, {%1, %2};" : "=l"(r) : "f"(a), "f"(b));
    return r;
}
__device__ __forceinline__ void ffma2(ull& c, ull a, ull b) {
    asm("fma.rn.f32x2 %0, %1, %2, %0;" : "+l"(c) : "l"(a), "l"(b));
}
__device__ __forceinline__ float pksum(ull c) {
    float lo, hi;
    asm("mov.b64 {%0, %1}, %2;" : "=f"(lo), "=f"(hi) : "l"(c));
    return lo + hi;
}

__global__ void __launch_bounds__(256, 4) cantor_moe_kernel(
    const float* __restrict__ x,
    const float* __restrict__ fingerprints,
    const float* __restrict__ ln_gamma,
    const float* __restrict__ ln_beta,
    const float* __restrict__ w1,
    const float* __restrict__ b1,
    const float* __restrict__ w2,
    const float* __restrict__ b2,
    const float* __restrict__ alpha,
    const float* __restrict__ wv,
    const float* __restrict__ penta,
    const float* __restrict__ betas,
    const float* __restrict__ wout,
    const float* __restrict__ pos_embed,
    const float* __restrict__ temperature,
    float* __restrict__ out)
{
    __shared__ __align__(16) float xnsm[2][8][S_];   // 4 KB normalized active slices
    __shared__ __align__(16) float Vsm[2][8][DK_];   // 8 KB unscaled V
    __shared__ __align__(16) float recA[2][8][S_];   // 4 KB rec d-half 0 (scaled)
    __shared__ __align__(16) float recB[2][8][S_];   // 4 KB rec d-half 1 (scaled)
    __shared__ float scalesm[2][8];
    __shared__ float Vpsm[2][8][5];
    __shared__ float w_esm[2];

    const int p    = blockIdx.x;
    const int tid  = threadIdx.x;
    const int warp = tid >> 5;
    const int lane = tid & 31;

    // ---------------- expert selection (redundant per-thread) ----------------
    const float fp = __ldg(fingerprints + p);
    int nact = 0, e0 = 0, e1 = -1;
    {
        const int base = (int)floorf(fp * 16.0f);
#pragma unroll
        for (int dd = -1; dd <= 1; ++dd) {
            const int ee = base + dd;
            if (ee < 0 || ee >= E_) continue;
            const float fmn = fmaxf(0.0f, (float)ee * 0.0625f - 0.03125f);
            const float fmx = fminf(1.0f, (float)(ee + 1) * 0.0625f + 0.03125f);
            if (fp >= fmn && fp < fmx) {
                if (nact == 0) e0 = ee; else if (nact == 1) e1 = ee;
                ++nact;
            }
        }
        if (nact > 2) nact = 2;
        if (nact < 2) e1 = -1;
    }

    // ---------------- LayerNorm: warp w = batch b; 2-pass ----------------
    {
        const int b = warp;
        const float* xr = x + ((size_t)b * P_ + p) * D_;
        float s = 0.f, ss = 0.f;
#pragma unroll
        for (int it = 0; it < 8; ++it) {
            const float4 xv = __ldg((const float4*)xr + it * 32 + lane);
            s  += xv.x + xv.y + xv.z + xv.w;
            ss += xv.x * xv.x + xv.y * xv.y + xv.z * xv.z + xv.w * xv.w;
        }
#pragma unroll
        for (int o = 16; o; o >>= 1) {
            s  += __shfl_xor_sync(~0u, s, o);
            ss += __shfl_xor_sync(~0u, ss, o);
        }
        const float mu   = s * (1.0f / D_);
        const float var  = ss * (1.0f / D_) - mu * mu;
        const float rstd = rsqrtf(var + 1e-5f);
        const int kk = lane >> 4;
        if (kk < nact) {
            const int ee = kk ? e1 : e0;
            const int f4 = ee * 16 + (lane & 15);
            const float4 xv = __ldg((const float4*)xr + f4);
            const float4 gm = __ldg((const float4*)ln_gamma + f4);
            const float4 bt = __ldg((const float4*)ln_beta + f4);
            float4 o4;
            o4.x = (xv.x - mu) * rstd * gm.x + bt.x;
            o4.y = (xv.y - mu) * rstd * gm.y + bt.y;
            o4.z = (xv.z - mu) * rstd * gm.z + bt.z;
            o4.w = (xv.w - mu) * rstd * gm.w + bt.w;
            *(float4*)&xnsm[kk][b][(lane & 15) * 4] = o4;
        }
    }
    __syncthreads();   // sync1

    if (nact == 2) {
        const int k = tid >> 7;
        const int g = tid & 127;
        const int e = k ? e1 : e0;

        // ---------- phase 2: gate (all 128) then V (all 128, packed) ----------
        {
            const int b = g >> 4, j = g & 15;
            const float* W1 = w1 + e * (S_ * H_);
            float acc = __ldg(b1 + e * H_ + j);
#pragma unroll
            for (int s4 = 0; s4 < 16; ++s4) {
                const float4 xf = *(const float4*)&xnsm[k][b][s4 * 4];
                acc += xf.x * __ldg(W1 + (s4 * 4 + 0) * H_ + j)
                     + xf.y * __ldg(W1 + (s4 * 4 + 1) * H_ + j)
                     + xf.z * __ldg(W1 + (s4 * 4 + 2) * H_ + j)
                     + xf.w * __ldg(W1 + (s4 * 4 + 3) * H_ + j);
            }
            float t = gelu_exact(acc) * __ldg(w2 + e * H_ + j);
#pragma unroll
            for (int o = 8; o; o >>= 1) t += __shfl_down_sync(~0u, t, o, 16);
            if (j == 0) {
                const float gate = sigm(t + __ldg(b2 + e));
                const float aw   = sigm(__ldg(alpha + e));
                scalesm[k][b] = gate * aw + (1.0f - aw);
            }
        }
        {
            const int d = g;
            const float* WV = wv + e * (S_ * DK_);
            ull acc2[8];
#pragma unroll
            for (int b = 0; b < 8; ++b) acc2[b] = 0ull;
#pragma unroll
            for (int s4 = 0; s4 < 16; ++s4) {
                const float q0 = __ldg(WV + (s4 * 4 + 0) * DK_ + d);
                const float q1 = __ldg(WV + (s4 * 4 + 1) * DK_ + d);
                const float q2 = __ldg(WV + (s4 * 4 + 2) * DK_ + d);
                const float q3 = __ldg(WV + (s4 * 4 + 3) * DK_ + d);
                const ull q01 = pk(q0, q1), q23 = pk(q2, q3);
#pragma unroll
                for (int b = 0; b < 8; ++b) {
                    const ulonglong2 xp = *(const ulonglong2*)&xnsm[k][b][s4 * 4];
                    ffma2(acc2[b], xp.x, q01);
                    ffma2(acc2[b], xp.y, q23);
                }
            }
#pragma unroll
            for (int b = 0; b < 8; ++b) Vsm[k][b][d] = pksum(acc2[b]);
        }
        __syncthreads();   // sync2

        // ---------- phase 3: rec (all 128, packed) then Vp + w_e ----------
        {
            const int s_idx = g & 63, half = g >> 6;
            const float* WO = wout + e * (DK_ * S_) + half * 64 * S_;
            ull acc2[8];
#pragma unroll
            for (int b = 0; b < 8; ++b) acc2[b] = 0ull;
#pragma unroll
            for (int d4 = 0; d4 < 16; ++d4) {
                const float q0 = __ldg(WO + (d4 * 4 + 0) * S_ + s_idx);
                const float q1 = __ldg(WO + (d4 * 4 + 1) * S_ + s_idx);
                const float q2 = __ldg(WO + (d4 * 4 + 2) * S_ + s_idx);
                const float q3 = __ldg(WO + (d4 * 4 + 3) * S_ + s_idx);
                const ull q01 = pk(q0, q1), q23 = pk(q2, q3);
#pragma unroll
                for (int b = 0; b < 8; ++b) {
                    const ulonglong2 vp2 = *(const ulonglong2*)&Vsm[k][b][half * 64 + d4 * 4];
                    ffma2(acc2[b], vp2.x, q01);
                    ffma2(acc2[b], vp2.y, q23);
                }
            }
            if (half == 0) {
#pragma unroll
                for (int b = 0; b < 8; ++b) recA[k][b][s_idx] = pksum(acc2[b]) * scalesm[k][b];
            } else {
#pragma unroll
                for (int b = 0; b < 8; ++b) recB[k][b][s_idx] = pksum(acc2[b]) * scalesm[k][b];
            }
        }
        {
            const int wg = g >> 5;    // 0..3 within group
            const float4 vvA = *(const float4*)&Vsm[k][wg][lane * 4];
            const float4 vvB = *(const float4*)&Vsm[k][wg + 4][lane * 4];
            float invn = 0.f;
            float4 pv = make_float4(0.f, 0.f, 0.f, 0.f);
#pragma unroll
            for (int t = 0; t < 10; ++t) {
                const int v = t >> 1;
                const int b = (t & 1) * 4 + wg;
                if ((t & 1) == 0) {
                    pv = __ldg((const float4*)(penta + (e * 5 + v) * DK_) + lane);
                    float nn = pv.x * pv.x + pv.y * pv.y + pv.z * pv.z + pv.w * pv.w;
#pragma unroll
                    for (int o = 16; o; o >>= 1) nn += __shfl_xor_sync(~0u, nn, o);
                    invn = rsqrtf(nn);
                }
                const float4 vv = (t & 1) ? vvB : vvA;
                float pd = pv.x * vv.x + pv.y * vv.y + pv.z * vv.z + pv.w * vv.w;
#pragma unroll
                for (int o = 16; o; o >>= 1) pd += __shfl_xor_sync(~0u, pd, o);
                if (lane == 0)
                    Vpsm[k][b][v] = pd * invn * scalesm[k][b];
            }
            if (wg == 0) {
                const float4 pe = __ldg((const float4*)(pos_embed + e * DK_) + lane);
                float pm = pe.x + pe.y + pe.z + pe.w;
#pragma unroll
                for (int o = 16; o; o >>= 1) pm += __shfl_xor_sync(~0u, pm, o);
                if (lane == 0) {
                    float sb = 0.f, cnt = 0.f;
#pragma unroll
                    for (int kk = 0; kk < 4; ++kk) {
                        const int off = (kk == 0) ? -2 : (kk == 1) ? -1 : (kk == 2) ? 1 : 2;
                        const int nb = e + off;
                        if (nb >= 0 && nb < E_) { sb += sigm(__ldg(betas + e * 4 + kk)); cnt += 1.f; }
                    }
                    w_esm[k] = sigm(pm * (1.0f / DK_)) * (1.0f + sb / cnt);
                }
            }
        }
    } else {
        // ================= nact == 1: all 256 threads on expert e0 =================
        const int e = e0;
        // ---------- phase 2: V (tid<128, packed) || gate (tid>=128) ----------
        if (tid < 128) {
            const int d = tid;
            const float* WV = wv + e * (S_ * DK_);
            ull acc2[8];
#pragma unroll
            for (int b = 0; b < 8; ++b) acc2[b] = 0ull;
#pragma unroll
            for (int s4 = 0; s4 < 16; ++s4) {
                const float q0 = __ldg(WV + (s4 * 4 + 0) * DK_ + d);
                const float q1 = __ldg(WV + (s4 * 4 + 1) * DK_ + d);
                const float q2 = __ldg(WV + (s4 * 4 + 2) * DK_ + d);
                const float q3 = __ldg(WV + (s4 * 4 + 3) * DK_ + d);
                const ull q01 = pk(q0, q1), q23 = pk(q2, q3);
#pragma unroll
                for (int b = 0; b < 8; ++b) {
                    const ulonglong2 xp = *(const ulonglong2*)&xnsm[0][b][s4 * 4];
                    ffma2(acc2[b], xp.x, q01);
                    ffma2(acc2[b], xp.y, q23);
                }
            }
#pragma unroll
            for (int b = 0; b < 8; ++b) Vsm[0][b][d] = pksum(acc2[b]);
        } else {
            const int gg = tid - 128;
            const int b = gg >> 4, j = gg & 15;
            const float* W1 = w1 + e * (S_ * H_);
            float acc = __ldg(b1 + e * H_ + j);
#pragma unroll
            for (int s4 = 0; s4 < 16; ++s4) {
                const float4 xf = *(const float4*)&xnsm[0][b][s4 * 4];
                acc += xf.x * __ldg(W1 + (s4 * 4 + 0) * H_ + j)
                     + xf.y * __ldg(W1 + (s4 * 4 + 1) * H_ + j)
                     + xf.z * __ldg(W1 + (s4 * 4 + 2) * H_ + j)
                     + xf.w * __ldg(W1 + (s4 * 4 + 3) * H_ + j);
            }
            float t = gelu_exact(acc) * __ldg(w2 + e * H_ + j);
#pragma unroll
            for (int o = 8; o; o >>= 1) t += __shfl_down_sync(~0u, t, o, 16);
            if (j == 0) {
                const float gate = sigm(t + __ldg(b2 + e));
                const float aw   = sigm(__ldg(alpha + e));
                scalesm[0][b] = gate * aw + (1.0f - aw);
            }
        }
        __syncthreads();   // sync2

        // ---------- phase 3: rec (tid<128, packed) || Vp + w_e (tid>=128) ----------
        if (tid < 128) {
            const int s_idx = tid & 63, half = tid >> 6;
            const float* WO = wout + e * (DK_ * S_) + half * 64 * S_;
            ull acc2[8];
#pragma unroll
            for (int b = 0; b < 8; ++b) acc2[b] = 0ull;
#pragma unroll
            for (int d4 = 0; d4 < 16; ++d4) {
                const float q0 = __ldg(WO + (d4 * 4 + 0) * S_ + s_idx);
                const float q1 = __ldg(WO + (d4 * 4 + 1) * S_ + s_idx);
                const float q2 = __ldg(WO + (d4 * 4 + 2) * S_ + s_idx);
                const float q3 = __ldg(WO + (d4 * 4 + 3) * S_ + s_idx);
                const ull q01 = pk(q0, q1), q23 = pk(q2, q3);
#pragma unroll
                for (int b = 0; b < 8; ++b) {
                    const ulonglong2 vp2 = *(const ulonglong2*)&Vsm[0][b][half * 64 + d4 * 4];
                    ffma2(acc2[b], vp2.x, q01);
                    ffma2(acc2[b], vp2.y, q23);
                }
            }
            if (half == 0) {
#pragma unroll
                for (int b = 0; b < 8; ++b) recA[0][b][s_idx] = pksum(acc2[b]) * scalesm[0][b];
            } else {
#pragma unroll
                for (int b = 0; b < 8; ++b) recB[0][b][s_idx] = pksum(acc2[b]) * scalesm[0][b];
            }
        } else {
            const int wg = (tid - 128) >> 5;   // 0..3
            const float4 vvA = *(const float4*)&Vsm[0][wg][lane * 4];
            const float4 vvB = *(const float4*)&Vsm[0][wg + 4][lane * 4];
            float invn = 0.f;
            float4 pv = make_float4(0.f, 0.f, 0.f, 0.f);
#pragma unroll
            for (int t = 0; t < 10; ++t) {
                const int v = t >> 1;
                const int b = (t & 1) * 4 + wg;
                if ((t & 1) == 0) {
                    pv = __ldg((const float4*)(penta + (e * 5 + v) * DK_) + lane);
                    float nn = pv.x * pv.x + pv.y * pv.y + pv.z * pv.z + pv.w * pv.w;
#pragma unroll
                    for (int o = 16; o; o >>= 1) nn += __shfl_xor_sync(~0u, nn, o);
                    invn = rsqrtf(nn);
                }
                const float4 vv = (t & 1) ? vvB : vvA;
                float pd = pv.x * vv.x + pv.y * vv.y + pv.z * vv.z + pv.w * vv.w;
#pragma unroll
                for (int o = 16; o; o >>= 1) pd += __shfl_xor_sync(~0u, pd, o);
                if (lane == 0)
                    Vpsm[0][b][v] = pd * invn * scalesm[0][b];
            }
            if (wg == 0) {
                const float4 pe = __ldg((const float4*)(pos_embed + e * DK_) + lane);
                float pm = pe.x + pe.y + pe.z + pe.w;
#pragma unroll
                for (int o = 16; o; o >>= 1) pm += __shfl_xor_sync(~0u, pm, o);
                if (lane == 0) {
                    float sb = 0.f, cnt = 0.f;
#pragma unroll
                    for (int kk = 0; kk < 4; ++kk) {
                        const int off = (kk == 0) ? -2 : (kk == 1) ? -1 : (kk == 2) ? 1 : 2;
                        const int nb = e + off;
                        if (nb >= 0 && nb < E_) { sb += sigm(__ldg(betas + e * 4 + kk)); cnt += 1.f; }
                    }
                    w_esm[0] = sigm(pm * (1.0f / DK_)) * (1.0f + sb / cnt);
                }
            }
        }
    }
    __syncthreads();   // sync3

    // -------- epilogue: inline fused; out = x + fused * rec on active slices --------
    {
        const int b = tid >> 5;              // one warp per batch
        float den = 0.f;
        for (int kk = 0; kk < nact; ++kk) den += w_esm[kk];
        den = fmaxf(den, 1e-6f);
        float fs = 0.f;
#pragma unroll
        for (int v = 0; v < 5; ++v) {
            float nv = 0.f;
            for (int kk = 0; kk < nact; ++kk) nv += Vpsm[kk][b][v] * w_esm[kk];
            fs += nv;
        }
        const float fused = (fs / den) * 0.2f / fabsf(__ldg(temperature));

        const float* xr  = x   + ((size_t)b * P_ + p) * D_;
        float*       orw = out + ((size_t)b * P_ + p) * D_;
#pragma unroll
        for (int it = 0; it < 8; ++it) {
            const int f4 = it * 32 + lane;
            float4 xv = __ldg((const float4*)xr + f4);
            const int ee = f4 >> 4;
            const int kk = (ee == e0) ? 0 : ((ee == e1) ? 1 : -1);
            if (kk >= 0) {
                const int si = (f4 & 15) * 4;
                const float4 ra = *(const float4*)&recA[kk][b][si];
                const float4 rb = *(const float4*)&recB[kk][b][si];
                xv.x += fused * (ra.x + rb.x);
                xv.y += fused * (ra.y + rb.y);
                xv.z += fused * (ra.z + rb.z);
                xv.w += fused * (ra.w + rb.w);
            }
            ((float4*)orw)[f4] = xv;
        }
    }
}

} // namespace

extern "C" void kernel_launch(void* const* d_in, const int* in_sizes, int n_in,
                              void* d_out, int out_size)
{
    (void)in_sizes; (void)n_in; (void)out_size;
    cantor_moe_kernel<<<P_, 256>>>(
        (const float*)d_in[0],   // x
        (const float*)d_in[1],   // fingerprints
        (const float*)d_in[2],   // ln_gamma
        (const float*)d_in[3],   // ln_beta
        (const float*)d_in[4],   // w1
        (const float*)d_in[5],   // b1
        (const float*)d_in[6],   // w2
        (const float*)d_in[7],   // b2
        (const float*)d_in[8],   // alpha
        (const float*)d_in[9],   // wv
        (const float*)d_in[10],  // penta
        (const float*)d_in[11],  // betas
        (const float*)d_in[12],  // wout
        (const float*)d_in[13],  // pos_embed
        (const float*)d_in[14],  // temperature
        (float*)d_out);
}